// round 1
// baseline (speedup 1.0000x reference)
#include <cuda_runtime.h>
#include <cstdint>

// ---------------- problem constants ----------------
#define BQ   4
#define DQ   64
#define HQ   64
#define WQ   64
#define HWQ  4096
#define SQ   64
#define NQ   8192
#define KQ   4
#define D9   576
#define IN_DIM 580
#define KP0  592          // 580 padded to multiple of 16
#define HID  256
#define NROW 262144       // B*N*8 MLP rows

// ---------------- device scratch (static, no runtime alloc) ----------------
__device__ float g_feat_rows[(size_t)BQ * HWQ * D9];   // (B,hw,D9)
__device__ int   g_segm[BQ * HWQ];
__device__ float g_top4v[BQ * SQ * KQ];
__device__ int   g_top4i[BQ * SQ * KQ];
__device__ float g_W0p[KP0 * HID];                     // zero-padded w0
__device__ float g_X [(size_t)NROW * KP0];
__device__ float g_H1[(size_t)NROW * HID];
__device__ float g_H2[(size_t)NROW * HID];
__device__ float g_cw[NROW];

// ---------------- small helpers ----------------
__device__ __forceinline__ unsigned f2t(float x) {
    unsigned r;
    asm("cvt.rna.tf32.f32 %0, %1;" : "=r"(r) : "f"(x));
    return r;
}
__device__ __forceinline__ void split2(float x, unsigned& hi, unsigned& lo) {
    hi = f2t(x);
    float h = __uint_as_float(hi);
    lo = f2t(x - h);
}
__device__ __forceinline__ void mma8(float* c,
                                     unsigned a0, unsigned a1, unsigned a2, unsigned a3,
                                     unsigned b0, unsigned b1) {
    asm volatile(
        "mma.sync.aligned.m16n8k8.row.col.f32.tf32.tf32.f32 "
        "{%0,%1,%2,%3},{%4,%5,%6,%7},{%8,%9},{%0,%1,%2,%3};\n"
        : "+f"(c[0]), "+f"(c[1]), "+f"(c[2]), "+f"(c[3])
        : "r"(a0), "r"(a1), "r"(a2), "r"(a3), "r"(b0), "r"(b1));
}

// top-4 insertion, matching lax.top_k tie semantics (value desc, index asc)
__device__ __forceinline__ void ins4(float v[4], int id[4], float val, int p) {
    if (!(val > v[3] || (val == v[3] && p < id[3]))) return;
    int pos = 3;
    while (pos > 0 && (val > v[pos - 1] || (val == v[pos - 1] && p < id[pos - 1]))) pos--;
    for (int q = 3; q > pos; q--) { v[q] = v[q - 1]; id[q] = id[q - 1]; }
    v[pos] = val; id[pos] = p;
}

// ---------------- kernels ----------------

// pad w0 (580x256) -> g_W0p (592x256) with zero rows
__global__ void k_prepw0(const float* __restrict__ w0) {
    int t = blockIdx.x * blockDim.x + threadIdx.x;
    if (t >= KP0 * HID) return;
    int r = t / HID;
    g_W0p[t] = (r < IN_DIM) ? w0[t] : 0.0f;
}

// F.unfold(feat, 3, padding=1) reshaped to (B, hw, D9), channel order c*9+ki*3+kj
__global__ void k_unfold(const float* __restrict__ feat) {
    size_t tid = (size_t)blockIdx.x * blockDim.x + threadIdx.x;
    const size_t total = (size_t)BQ * HWQ * D9;
    if (tid >= total) return;
    int c9 = (int)(tid % D9);
    size_t r = tid / D9;
    int p = (int)(r % HWQ);
    int b = (int)(r / HWQ);
    int c = c9 / 9, kk = c9 % 9;
    int ki = kk / 3, kj = kk % 3;
    int i = p / WQ, j = p % WQ;
    int ii = i + ki - 1, jj = j + kj - 1;
    float v = 0.0f;
    if (ii >= 0 && ii < HQ && jj >= 0 && jj < WQ)
        v = feat[(((size_t)b * DQ + c) * HQ + ii) * WQ + jj];
    g_feat_rows[tid] = v;
}

// argmax over S per (b, pixel) — first occurrence on ties (strict >)
__global__ void k_argmax(const float* __restrict__ attn) {
    int t = blockIdx.x * blockDim.x + threadIdx.x;
    if (t >= BQ * HWQ) return;
    const float* row = attn + (size_t)t * SQ;
    float best = row[0]; int bi = 0;
    for (int s = 1; s < SQ; s++) {
        float v = row[s];
        if (v > best) { best = v; bi = s; }
    }
    g_segm[t] = bi;
}

// top-4 of attn[b, :, s] for each of the 256 (b,s) rows — one warp per row
__global__ void k_top4(const float* __restrict__ attn) {
    int gw = (blockIdx.x * blockDim.x + threadIdx.x) >> 5;
    int lane = threadIdx.x & 31;
    int wl = threadIdx.x >> 5;
    __shared__ float sv[8][32][4];
    __shared__ int   si[8][32][4];
    if (gw >= BQ * SQ) return;
    int b = gw / SQ, s = gw % SQ;
    float v[4]  = {-1e30f, -1e30f, -1e30f, -1e30f};
    int   id[4] = {0x7fffffff, 0x7fffffff, 0x7fffffff, 0x7fffffff};
    for (int p = lane; p < HWQ; p += 32) {
        float val = attn[((size_t)b * HWQ + p) * SQ + s];
        ins4(v, id, val, p);
    }
    for (int q = 0; q < 4; q++) { sv[wl][lane][q] = v[q]; si[wl][lane][q] = id[q]; }
    __syncwarp();
    if (lane == 0) {
        float fv[4]  = {-1e30f, -1e30f, -1e30f, -1e30f};
        int   fi[4]  = {0x7fffffff, 0x7fffffff, 0x7fffffff, 0x7fffffff};
        for (int l = 0; l < 32; l++)
            for (int q = 0; q < 4; q++)
                ins4(fv, fi, sv[wl][l][q], si[wl][l][q]);
        for (int q = 0; q < 4; q++) {
            g_top4v[gw * 4 + q] = fv[q];
            g_top4i[gw * 4 + q] = fi[q];
        }
    }
}

// build X rows (8 per query) + combined weights g_cw
__global__ void k_build(const float* __restrict__ coord,
                        const float* __restrict__ cell) {
    int q = blockIdx.x;          // 0..32767
    int b = q >> 13;
    int n = q & 8191;
    __shared__ unsigned srcoff[8];
    __shared__ float    tail[8][4];
    __shared__ float    cwsh[8];
    if (threadIdx.x == 0) {
        size_t cb = ((size_t)b * NQ + n) * 2;
        float c0 = coord[cb], c1 = coord[cb + 1];
        float rc0 = cell[cb] * (float)HQ, rc1 = cell[cb + 1] * (float)WQ;

        // ---- attention branch ----
        float pcf0 = (c0 + 1.0f) / 2.0f * (float)HQ;
        float pcf1 = (c1 + 1.0f) / 2.0f * (float)WQ;
        int pc0 = (int)pcf0; pc0 = max(0, min(HWQ - 1, pc0));
        int pc1 = (int)pcf1; pc1 = max(0, min(HWQ - 1, pc1));
        int pc1d = pc0 * HQ + pc1;
        pc1d = max(0, min(HWQ - 1, pc1d));
        int segm = g_segm[b * HWQ + pc1d];
        const float* tv = &g_top4v[(b * SQ + segm) * 4];
        const int*   ti = &g_top4i[(b * SQ + segm) * 4];
        float sum = tv[0] + tv[1] + tv[2] + tv[3];
        for (int k = 0; k < 4; k++) {
            int rc = ti[k];
            int rrc = rc - pc1d;
            float rel0 = (float)(rrc >> 6) * (1.0f / (float)HQ); // floor-div by 64
            float rel1 = (float)(rrc & 63) * (1.0f / (float)WQ); // python mod 64
            srcoff[k] = (unsigned)rc * D9;                       // batch-0 gather (faithful)
            tail[k][0] = rel0; tail[k][1] = rel1;
            tail[k][2] = rc0;  tail[k][3] = rc1;
            cwsh[k] = 0.5f * (tv[k] / sum);
        }

        // ---- local ensemble ----
        const float offv[4][2] = {{-1.f, -1.f}, {-1.f, 1.f}, {1.f, -1.f}, {1.f, 1.f}};
        float area[4];
        for (int j = 0; j < 4; j++) {
            float rx = 1.0f / (float)HQ, ry = 1.0f / (float)WQ;
            float cc0 = c0 + offv[j][0] * rx + 1e-6f;
            float cc1 = c1 + offv[j][1] * ry + 1e-6f;
            cc0 = fminf(fmaxf(cc0, -1.0f + 1e-6f), 1.0f - 1e-6f);
            cc1 = fminf(fmaxf(cc1, -1.0f + 1e-6f), 1.0f - 1e-6f);
            float fy = ((cc0 + 1.0f) * (float)HQ - 1.0f) / 2.0f;
            float fx = ((cc1 + 1.0f) * (float)WQ - 1.0f) / 2.0f;
            int iy = (int)rintf(fy); iy = max(0, min(HQ - 1, iy));
            int ix = (int)rintf(fx); ix = max(0, min(WQ - 1, ix));
            int flat = iy * WQ + ix;
            float qc0 = -1.0f + (2.0f * (float)iy + 1.0f) / (float)HQ;
            float qc1 = -1.0f + (2.0f * (float)ix + 1.0f) / (float)WQ;
            float r0 = (c0 - qc0) * (float)HQ;
            float r1 = (c1 - qc1) * (float)WQ;
            srcoff[4 + j] = (unsigned)(b * HWQ + flat) * D9;
            tail[4 + j][0] = r0; tail[4 + j][1] = r1;
            tail[4 + j][2] = rc0; tail[4 + j][3] = rc1;
            area[j] = fabsf(r0 * r1) + 1e-9f;
        }
        float tot = area[0] + area[1] + area[2] + area[3];
        for (int j = 0; j < 4; j++) cwsh[4 + j] = 0.5f * (area[3 - j] / tot);
    }
    __syncthreads();
    int w = threadIdx.x >> 5, lane = threadIdx.x & 31;
    if (lane == 0) g_cw[q * 8 + w] = cwsh[w];
    size_t xb = ((size_t)q * 8 + w) * KP0;
    const float* src = g_feat_rows + srcoff[w];
    for (int c = lane; c < KP0; c += 32) {
        float val;
        if (c < D9)          val = src[c];
        else if (c < IN_DIM) val = tail[w][c - D9];
        else                 val = 0.0f;
        g_X[xb + c] = val;
    }
}

// C[M x 256] = relu(A[M x Kd] @ W[Kd x 256] + bias), 3xTF32 mma
// BM=128 BN=64 BK=16, 256 threads, grid = (4 ntiles, M/128)
__global__ void __launch_bounds__(256)
k_gemm(const float* __restrict__ A, int lda, int Kd,
       const float* __restrict__ Wt,
       const float* __restrict__ bias,
       float* __restrict__ C, int doRelu) {
    __shared__ float As[128][17];
    __shared__ float Bs[16][68];
    int tid = threadIdx.x;
    int m0 = blockIdx.y * 128;
    int n0 = blockIdx.x * 64;
    int warp = tid >> 5, lane = tid & 31;
    int wm = warp & 3, wn = warp >> 2;     // 4 x 2 warp grid, warp tile 32x32
    int g = lane >> 2, tg = lane & 3;

    float acc[2][4][4];
#pragma unroll
    for (int mf = 0; mf < 2; mf++)
#pragma unroll
        for (int nf = 0; nf < 4; nf++)
#pragma unroll
            for (int ci = 0; ci < 4; ci++) acc[mf][nf][ci] = 0.0f;

    for (int kk = 0; kk < Kd; kk += 16) {
        float4 av[2];
#pragma unroll
        for (int i = 0; i < 2; i++) {
            int idx = tid + i * 256;
            int r = idx >> 2, c4 = idx & 3;
            av[i] = *(const float4*)(A + (size_t)(m0 + r) * lda + kk + c4 * 4);
        }
        int br = tid >> 4, bc = tid & 15;
        float4 bv = *(const float4*)(Wt + (size_t)(kk + br) * HID + n0 + bc * 4);
        __syncthreads();   // previous tile's compute done
#pragma unroll
        for (int i = 0; i < 2; i++) {
            int idx = tid + i * 256;
            int r = idx >> 2, c4 = idx & 3;
            As[r][c4 * 4 + 0] = av[i].x; As[r][c4 * 4 + 1] = av[i].y;
            As[r][c4 * 4 + 2] = av[i].z; As[r][c4 * 4 + 3] = av[i].w;
        }
        Bs[br][bc * 4 + 0] = bv.x; Bs[br][bc * 4 + 1] = bv.y;
        Bs[br][bc * 4 + 2] = bv.z; Bs[br][bc * 4 + 3] = bv.w;
        __syncthreads();

#pragma unroll
        for (int ks = 0; ks < 2; ks++) {
            int kb = ks * 8;
            unsigned ah[2][4], al[2][4];
#pragma unroll
            for (int mf = 0; mf < 2; mf++) {
                int rb = wm * 32 + mf * 16;
                split2(As[rb + g    ][kb + tg    ], ah[mf][0], al[mf][0]);
                split2(As[rb + g + 8][kb + tg    ], ah[mf][1], al[mf][1]);
                split2(As[rb + g    ][kb + tg + 4], ah[mf][2], al[mf][2]);
                split2(As[rb + g + 8][kb + tg + 4], ah[mf][3], al[mf][3]);
            }
            unsigned bh[4][2], bl[4][2];
#pragma unroll
            for (int nf = 0; nf < 4; nf++) {
                int cb = wn * 32 + nf * 8 + g;
                split2(Bs[kb + tg    ][cb], bh[nf][0], bl[nf][0]);
                split2(Bs[kb + tg + 4][cb], bh[nf][1], bl[nf][1]);
            }
#pragma unroll
            for (int mf = 0; mf < 2; mf++)
#pragma unroll
                for (int nf = 0; nf < 4; nf++) {
                    mma8(acc[mf][nf], ah[mf][0], ah[mf][1], ah[mf][2], ah[mf][3],
                         bl[nf][0], bl[nf][1]);                       // hi*lo
                    mma8(acc[mf][nf], al[mf][0], al[mf][1], al[mf][2], al[mf][3],
                         bh[nf][0], bh[nf][1]);                       // lo*hi
                    mma8(acc[mf][nf], ah[mf][0], ah[mf][1], ah[mf][2], ah[mf][3],
                         bh[nf][0], bh[nf][1]);                       // hi*hi
                }
        }
        __syncthreads();
    }

#pragma unroll
    for (int mf = 0; mf < 2; mf++)
#pragma unroll
        for (int nf = 0; nf < 4; nf++)
#pragma unroll
            for (int ci = 0; ci < 4; ci++) {
                int row = m0 + wm * 32 + mf * 16 + g + ((ci >= 2) ? 8 : 0);
                int col = n0 + wn * 32 + nf * 8 + tg * 2 + (ci & 1);
                float v = acc[mf][nf][ci] + bias[col];
                if (doRelu) v = fmaxf(v, 0.0f);
                C[(size_t)row * HID + col] = v;
            }
}

// last layer (256 -> 3) fused with the weighted ensemble reduction
__global__ void k_final(const float* __restrict__ w4, const float* __restrict__ b4,
                        float* __restrict__ out) {
    __shared__ float w4s[HID * 3];
    __shared__ float b4s[3];
    for (int i = threadIdx.x; i < HID * 3; i += blockDim.x) w4s[i] = w4[i];
    if (threadIdx.x < 3) b4s[threadIdx.x] = b4[threadIdx.x];
    __syncthreads();
    int warp = threadIdx.x >> 5, lane = threadIdx.x & 31;
    int q = blockIdx.x * 8 + warp;     // 0..32767
    float a0 = 0.f, a1 = 0.f, a2 = 0.f, scw = 0.f;
    for (int r = 0; r < 8; r++) {
        float cwv = g_cw[q * 8 + r];
        size_t hb = ((size_t)q * 8 + r) * HID;
        float s0 = 0.f, s1 = 0.f, s2 = 0.f;
        for (int c = lane; c < HID; c += 32) {
            float hv = g_H2[hb + c];
            s0 += hv * w4s[c * 3 + 0];
            s1 += hv * w4s[c * 3 + 1];
            s2 += hv * w4s[c * 3 + 2];
        }
        a0 += cwv * s0; a1 += cwv * s1; a2 += cwv * s2;
        scw += cwv;     // identical on all lanes
    }
#pragma unroll
    for (int o = 16; o > 0; o >>= 1) {
        a0 += __shfl_down_sync(0xffffffffu, a0, o);
        a1 += __shfl_down_sync(0xffffffffu, a1, o);
        a2 += __shfl_down_sync(0xffffffffu, a2, o);
    }
    if (lane == 0) {
        out[(size_t)q * 3 + 0] = a0 + scw * b4s[0];
        out[(size_t)q * 3 + 1] = a1 + scw * b4s[1];
        out[(size_t)q * 3 + 2] = a2 + scw * b4s[2];
    }
}

// ---------------- launch ----------------
extern "C" void kernel_launch(void* const* d_in, const int* in_sizes, int n_in,
                              void* d_out, int out_size) {
    const float* feat  = (const float*)d_in[0];
    const float* attn  = (const float*)d_in[1];
    const float* coord = (const float*)d_in[2];
    const float* cell  = (const float*)d_in[3];
    const float* w0 = (const float*)d_in[4];
    const float* b0 = (const float*)d_in[5];
    const float* w1 = (const float*)d_in[6];
    const float* b1 = (const float*)d_in[7];
    const float* w2 = (const float*)d_in[8];
    const float* b2 = (const float*)d_in[9];
    const float* w3 = (const float*)d_in[10];
    const float* b3 = (const float*)d_in[11];
    const float* w4 = (const float*)d_in[12];
    const float* b4 = (const float*)d_in[13];
    float* out = (float*)d_out;

    float *X, *H1, *H2, *W0p;
    cudaGetSymbolAddress((void**)&X,   g_X);
    cudaGetSymbolAddress((void**)&H1,  g_H1);
    cudaGetSymbolAddress((void**)&H2,  g_H2);
    cudaGetSymbolAddress((void**)&W0p, g_W0p);

    k_prepw0<<<(KP0 * HID + 255) / 256, 256>>>(w0);
    k_unfold<<<(int)(((size_t)BQ * HWQ * D9 + 255) / 256), 256>>>(feat);
    k_argmax<<<(BQ * HWQ + 255) / 256, 256>>>(attn);
    k_top4<<<32, 256>>>(attn);
    k_build<<<BQ * NQ, 256>>>(coord, cell);

    dim3 gg(4, NROW / 128);
    k_gemm<<<gg, 256>>>(X,  KP0, KP0, W0p, b0, H1, 1);
    k_gemm<<<gg, 256>>>(H1, HID, HID, w1,  b1, H2, 1);
    k_gemm<<<gg, 256>>>(H2, HID, HID, w2,  b2, H1, 1);
    k_gemm<<<gg, 256>>>(H1, HID, HID, w3,  b3, H2, 1);

    k_final<<<BQ * NQ / 8, 256>>>(w4, b4, out);
}

// round 2
// speedup vs baseline: 1.9930x; 1.9930x over previous
#include <cuda_runtime.h>
#include <cuda_bf16.h>
#include <cstdint>

// ---------------- problem constants ----------------
#define BQ   4
#define DQ   64
#define HQ   64
#define WQ   64
#define HWQ  4096
#define SQ   64
#define NQ   8192
#define KQ   4
#define D9   576
#define IN_DIM 580
#define KP0  592          // 580 padded to multiple of 16
#define HID  256
#define NROW 262144       // B*N*8 MLP rows
#define NCHUNK 16

// ---------------- device scratch ----------------
__device__ float    g_feat_rows[(size_t)BQ * HWQ * D9];   // (B,hw,D9) f32, 37.7MB
__device__ int      g_segm[BQ * HWQ];
__device__ float    g_partv[BQ * NCHUNK * SQ * KQ];
__device__ int      g_parti[BQ * NCHUNK * SQ * KQ];
__device__ float    g_top4v[BQ * SQ * KQ];
__device__ int      g_top4i[BQ * SQ * KQ];
__device__ uint32_t g_W0p32[KP0 * HID];                   // packed (hi|lo<<16) bf16
__device__ uint32_t g_Wp32[3 * HID * HID];
__device__ uint32_t g_H1[(size_t)NROW * HID];             // packed hidden activations
__device__ uint32_t g_H2[(size_t)NROW * HID];
__device__ int      g_rowsrc[NROW];
__device__ float    g_tail[(size_t)NROW * 4];
__device__ float    g_cw[NROW];

// ---------------- helpers ----------------
__device__ __forceinline__ unsigned short f2b(float x) {
    return __bfloat16_as_ushort(__float2bfloat16_rn(x));
}
__device__ __forceinline__ float b2f(unsigned short u) {
    return __bfloat162float(__ushort_as_bfloat16(u));
}
__device__ __forceinline__ uint32_t packsplit(float v) {
    unsigned short h = f2b(v);
    unsigned short l = f2b(v - b2f(h));
    return (uint32_t)h | ((uint32_t)l << 16);
}
__device__ __forceinline__ void mma_bf16(float* c, const unsigned* a,
                                         unsigned b0, unsigned b1) {
    asm volatile(
        "mma.sync.aligned.m16n8k16.row.col.f32.bf16.bf16.f32 "
        "{%0,%1,%2,%3},{%4,%5,%6,%7},{%8,%9},{%0,%1,%2,%3};\n"
        : "+f"(c[0]), "+f"(c[1]), "+f"(c[2]), "+f"(c[3])
        : "r"(a[0]), "r"(a[1]), "r"(a[2]), "r"(a[3]), "r"(b0), "r"(b1));
}
// top-4 insertion, lax.top_k tie semantics (value desc, index asc)
__device__ __forceinline__ void ins4(float v[4], int id[4], float val, int p) {
    if (!(val > v[3] || (val == v[3] && p < id[3]))) return;
    int pos = 3;
    while (pos > 0 && (val > v[pos - 1] || (val == v[pos - 1] && p < id[pos - 1]))) pos--;
    for (int q = 3; q > pos; q--) { v[q] = v[q - 1]; id[q] = id[q - 1]; }
    v[pos] = val; id[pos] = p;
}

// ---------------- prep: split weights into packed bf16 pairs ----------------
__global__ void k_prepw(const float* __restrict__ w0, const float* __restrict__ w1,
                        const float* __restrict__ w2, const float* __restrict__ w3) {
    int t = blockIdx.x * blockDim.x + threadIdx.x;
    const int n0 = KP0 * HID;
    if (t < n0) {
        int r = t / HID;
        float v = (r < IN_DIM) ? w0[t] : 0.0f;
        g_W0p32[t] = packsplit(v);
        return;
    }
    int t2 = t - n0;
    if (t2 >= 3 * HID * HID) return;
    int layer = t2 / (HID * HID);
    int i = t2 % (HID * HID);
    const float* w = (layer == 0) ? w1 : (layer == 1) ? w2 : w3;
    g_Wp32[t2] = packsplit(w[i]);
}

// ---------------- unfold ----------------
__global__ void k_unfold(const float* __restrict__ feat) {
    size_t tid = (size_t)blockIdx.x * blockDim.x + threadIdx.x;
    const size_t total = (size_t)BQ * HWQ * D9;
    if (tid >= total) return;
    int c9 = (int)(tid % D9);
    size_t r = tid / D9;
    int p = (int)(r % HWQ);
    int b = (int)(r / HWQ);
    int c = c9 / 9, kk = c9 % 9;
    int ki = kk / 3, kj = kk % 3;
    int i = p / WQ, j = p % WQ;
    int ii = i + ki - 1, jj = j + kj - 1;
    float v = 0.0f;
    if (ii >= 0 && ii < HQ && jj >= 0 && jj < WQ)
        v = feat[(((size_t)b * DQ + c) * HQ + ii) * WQ + jj];
    g_feat_rows[tid] = v;
}

// ---------------- argmax over S per (b,pixel) ----------------
__global__ void k_argmax(const float* __restrict__ attn) {
    int t = blockIdx.x * blockDim.x + threadIdx.x;
    if (t >= BQ * HWQ) return;
    const float* row = attn + (size_t)t * SQ;
    float best = row[0]; int bi = 0;
    for (int s = 1; s < SQ; s++) {
        float v = row[s];
        if (v > best) { best = v; bi = s; }
    }
    g_segm[t] = bi;
}

// ---------------- top4 stage A: coalesced partial top-4 per (b,chunk,s) --------
__global__ void k_top4a(const float* __restrict__ attn) {
    __shared__ float tile[32][SQ + 1];
    __shared__ float sv[4][SQ][4];
    __shared__ int   si[4][SQ][4];
    int b = blockIdx.x >> 4;
    int chunk = blockIdx.x & 15;
    int tid = threadIdx.x;
    int s = tid & 63, sub = tid >> 6;
    float v[4]  = {-1e30f, -1e30f, -1e30f, -1e30f};
    int   id[4] = {0x7fffffff, 0x7fffffff, 0x7fffffff, 0x7fffffff};
    for (int t8 = 0; t8 < 8; t8++) {
        int p0 = chunk * 256 + t8 * 32;
        __syncthreads();
        for (int i = tid; i < 32 * SQ; i += 256) {
            int r = i >> 6, c = i & 63;
            tile[r][c] = attn[((size_t)(b * HWQ) + p0 + r) * SQ + c];
        }
        __syncthreads();
        for (int rr = 0; rr < 8; rr++) {
            int r = sub * 8 + rr;
            ins4(v, id, tile[r][s], p0 + r);
        }
    }
    for (int q = 0; q < 4; q++) { sv[sub][s][q] = v[q]; si[sub][s][q] = id[q]; }
    __syncthreads();
    if (sub == 0) {
        float fv[4]  = {-1e30f, -1e30f, -1e30f, -1e30f};
        int   fi[4]  = {0x7fffffff, 0x7fffffff, 0x7fffffff, 0x7fffffff};
        for (int ss = 0; ss < 4; ss++)
            for (int q = 0; q < 4; q++)
                ins4(fv, fi, sv[ss][s][q], si[ss][s][q]);
        int base = ((b * NCHUNK + chunk) * SQ + s) * 4;
        for (int q = 0; q < 4; q++) { g_partv[base + q] = fv[q]; g_parti[base + q] = fi[q]; }
    }
}

// ---------------- top4 stage B: merge chunks ----------------
__global__ void k_top4b() {
    int t = threadIdx.x;            // 256 threads: (b,s)
    int b = t >> 6, s = t & 63;
    float v[4]  = {-1e30f, -1e30f, -1e30f, -1e30f};
    int   id[4] = {0x7fffffff, 0x7fffffff, 0x7fffffff, 0x7fffffff};
    for (int ch = 0; ch < NCHUNK; ch++) {
        int base = ((b * NCHUNK + ch) * SQ + s) * 4;
        for (int q = 0; q < 4; q++) ins4(v, id, g_partv[base + q], g_parti[base + q]);
    }
    int o = (b * SQ + s) * 4;
    for (int q = 0; q < 4; q++) { g_top4v[o + q] = v[q]; g_top4i[o + q] = id[q]; }
}

// ---------------- build: per-query gather offsets + tails + weights ----------
__global__ void k_build(const float* __restrict__ coord,
                        const float* __restrict__ cell) {
    int q = blockIdx.x * blockDim.x + threadIdx.x;
    if (q >= BQ * NQ) return;
    int b = q >> 13;
    size_t cb = (size_t)q * 2;
    float c0 = coord[cb], c1 = coord[cb + 1];
    float rc0 = cell[cb] * (float)HQ, rc1 = cell[cb + 1] * (float)WQ;

    // ---- attention branch ----
    float pcf0 = (c0 + 1.0f) / 2.0f * (float)HQ;
    float pcf1 = (c1 + 1.0f) / 2.0f * (float)WQ;
    int pc0 = (int)pcf0; pc0 = max(0, min(HWQ - 1, pc0));
    int pc1 = (int)pcf1; pc1 = max(0, min(HWQ - 1, pc1));
    int pc1d = pc0 * HQ + pc1;
    pc1d = max(0, min(HWQ - 1, pc1d));
    int segm = g_segm[b * HWQ + pc1d];
    const float* tv = &g_top4v[(b * SQ + segm) * 4];
    const int*   ti = &g_top4i[(b * SQ + segm) * 4];
    float sum = tv[0] + tv[1] + tv[2] + tv[3];
    for (int k = 0; k < 4; k++) {
        int rc = ti[k];
        int rrc = rc - pc1d;
        float rel0 = (float)(rrc >> 6) * (1.0f / (float)HQ); // floor-div 64
        float rel1 = (float)(rrc & 63) * (1.0f / (float)WQ); // python mod 64
        int rowr = q * 8 + k;
        g_rowsrc[rowr] = rc * D9;                            // batch-0 gather (faithful)
        g_tail[(size_t)rowr * 4 + 0] = rel0;
        g_tail[(size_t)rowr * 4 + 1] = rel1;
        g_tail[(size_t)rowr * 4 + 2] = rc0;
        g_tail[(size_t)rowr * 4 + 3] = rc1;
        g_cw[rowr] = 0.5f * (tv[k] / sum);
    }

    // ---- local ensemble ----
    const float offv[4][2] = {{-1.f, -1.f}, {-1.f, 1.f}, {1.f, -1.f}, {1.f, 1.f}};
    float area[4];
    for (int j = 0; j < 4; j++) {
        float rx = 1.0f / (float)HQ, ry = 1.0f / (float)WQ;
        float cc0 = c0 + offv[j][0] * rx + 1e-6f;
        float cc1 = c1 + offv[j][1] * ry + 1e-6f;
        cc0 = fminf(fmaxf(cc0, -1.0f + 1e-6f), 1.0f - 1e-6f);
        cc1 = fminf(fmaxf(cc1, -1.0f + 1e-6f), 1.0f - 1e-6f);
        float fy = ((cc0 + 1.0f) * (float)HQ - 1.0f) / 2.0f;
        float fx = ((cc1 + 1.0f) * (float)WQ - 1.0f) / 2.0f;
        int iy = (int)rintf(fy); iy = max(0, min(HQ - 1, iy));
        int ix = (int)rintf(fx); ix = max(0, min(WQ - 1, ix));
        int flat = iy * WQ + ix;
        float qc0 = -1.0f + (2.0f * (float)iy + 1.0f) / (float)HQ;
        float qc1 = -1.0f + (2.0f * (float)ix + 1.0f) / (float)WQ;
        float r0 = (c0 - qc0) * (float)HQ;
        float r1 = (c1 - qc1) * (float)WQ;
        int rowr = q * 8 + 4 + j;
        g_rowsrc[rowr] = (b * HWQ + flat) * D9;
        g_tail[(size_t)rowr * 4 + 0] = r0;
        g_tail[(size_t)rowr * 4 + 1] = r1;
        g_tail[(size_t)rowr * 4 + 2] = rc0;
        g_tail[(size_t)rowr * 4 + 3] = rc1;
        area[j] = fabsf(r0 * r1) + 1e-9f;
    }
    float tot = area[0] + area[1] + area[2] + area[3];
    for (int j = 0; j < 4; j++) g_cw[q * 8 + 4 + j] = 0.5f * (area[3 - j] / tot);
}

// ---------------- GEMM: C = pack(relu(A @ W + bias)), bf16x3 mma ----------------
// BM=128, BN=256(full), BK=16, 256 threads (8 warps, 2m x 4n, warp tile 64x64)
// MODE 0: A gathered f32 from g_feat_rows (+4-col tail tile), K=592 (37 tiles)
// MODE 1: A = packed (hi,lo) u32 hidden activations, K=256 (16 tiles)
template<int MODE>
__global__ void __launch_bounds__(256)
k_gemm(const uint32_t* __restrict__ A, const uint32_t* __restrict__ W,
       const float* __restrict__ bias, uint32_t* __restrict__ C) {
    constexpr int T = (MODE == 0) ? (KP0 / 16) : (HID / 16);
    __shared__ __align__(16) unsigned short AsH[128][24];
    __shared__ __align__(16) unsigned short AsL[128][24];
    __shared__ __align__(16) unsigned short BsH[256][24];
    __shared__ __align__(16) unsigned short BsL[256][24];

    int tid = threadIdx.x;
    int m0 = blockIdx.x * 128;
    int arow = tid >> 1, ahalf = tid & 1;
    int src = 0;
    if (MODE == 0) src = g_rowsrc[m0 + arow];

    float    af[8];
    uint32_t au[8];
    uint32_t bw[16];

    // ---- stage tile t into regs ----
    auto loadT = [&](int t) {
        int kk = t * 16;
        if (MODE == 0) {
            if (kk < D9) {
                float4 f0 = *(const float4*)&g_feat_rows[src + kk + ahalf * 8];
                float4 f1 = *(const float4*)&g_feat_rows[src + kk + ahalf * 8 + 4];
                af[0] = f0.x; af[1] = f0.y; af[2] = f0.z; af[3] = f0.w;
                af[4] = f1.x; af[5] = f1.y; af[6] = f1.z; af[7] = f1.w;
            } else {
#pragma unroll
                for (int j = 0; j < 8; j++) {
                    int c = ahalf * 8 + j;
                    af[j] = (c < 4) ? g_tail[(size_t)(m0 + arow) * 4 + c] : 0.0f;
                }
            }
        } else {
            const uint32_t* ap = A + (size_t)(m0 + arow) * HID + kk + ahalf * 8;
            uint4 u0 = *(const uint4*)ap;
            uint4 u1 = *(const uint4*)(ap + 4);
            au[0] = u0.x; au[1] = u0.y; au[2] = u0.z; au[3] = u0.w;
            au[4] = u1.x; au[5] = u1.y; au[6] = u1.z; au[7] = u1.w;
        }
#pragma unroll
        for (int r = 0; r < 16; r++) bw[r] = W[(size_t)(kk + r) * HID + tid];
    };
    auto storeT = [&]() {
#pragma unroll
        for (int j = 0; j < 8; j++) {
            unsigned short h, l;
            if (MODE == 0) {
                float v = af[j];
                h = f2b(v);
                l = f2b(v - b2f(h));
            } else {
                h = (unsigned short)(au[j] & 0xffff);
                l = (unsigned short)(au[j] >> 16);
            }
            AsH[arow][ahalf * 8 + j] = h;
            AsL[arow][ahalf * 8 + j] = l;
        }
#pragma unroll
        for (int r = 0; r < 16; r++) {
            BsH[tid][r] = (unsigned short)(bw[r] & 0xffff);
            BsL[tid][r] = (unsigned short)(bw[r] >> 16);
        }
    };

    int warp = tid >> 5, lane = tid & 31;
    int wm = warp & 1, wn = warp >> 1;
    int g = lane >> 2, tg = lane & 3;

    float acc[4][8][4];
#pragma unroll
    for (int mf = 0; mf < 4; mf++)
#pragma unroll
        for (int nf = 0; nf < 8; nf++)
#pragma unroll
            for (int ci = 0; ci < 4; ci++) acc[mf][nf][ci] = 0.0f;

    loadT(0);
    for (int t = 0; t < T; t++) {
        __syncthreads();
        storeT();
        __syncthreads();
        if (t + 1 < T) loadT(t + 1);

        unsigned aH[4][4], aL[4][4];
#pragma unroll
        for (int mf = 0; mf < 4; mf++) {
            int r0 = wm * 64 + mf * 16 + g;
            aH[mf][0] = *(const uint32_t*)&AsH[r0    ][2 * tg];
            aH[mf][1] = *(const uint32_t*)&AsH[r0 + 8][2 * tg];
            aH[mf][2] = *(const uint32_t*)&AsH[r0    ][2 * tg + 8];
            aH[mf][3] = *(const uint32_t*)&AsH[r0 + 8][2 * tg + 8];
            aL[mf][0] = *(const uint32_t*)&AsL[r0    ][2 * tg];
            aL[mf][1] = *(const uint32_t*)&AsL[r0 + 8][2 * tg];
            aL[mf][2] = *(const uint32_t*)&AsL[r0    ][2 * tg + 8];
            aL[mf][3] = *(const uint32_t*)&AsL[r0 + 8][2 * tg + 8];
        }
#pragma unroll
        for (int nf = 0; nf < 8; nf++) {
            int c0 = wn * 64 + nf * 8 + g;
            unsigned bH0 = *(const uint32_t*)&BsH[c0][2 * tg];
            unsigned bH1 = *(const uint32_t*)&BsH[c0][2 * tg + 8];
            unsigned bL0 = *(const uint32_t*)&BsL[c0][2 * tg];
            unsigned bL1 = *(const uint32_t*)&BsL[c0][2 * tg + 8];
#pragma unroll
            for (int mf = 0; mf < 4; mf++) {
                mma_bf16(acc[mf][nf], aH[mf], bH0, bH1);   // hi*hi
                mma_bf16(acc[mf][nf], aH[mf], bL0, bL1);   // hi*lo
                mma_bf16(acc[mf][nf], aL[mf], bH0, bH1);   // lo*hi
            }
        }
    }

    // ---- epilogue: bias + relu + pack(hi,lo) ----
#pragma unroll
    for (int nf = 0; nf < 8; nf++) {
        int col = wn * 64 + nf * 8 + tg * 2;
        float bv0 = bias[col], bv1 = bias[col + 1];
#pragma unroll
        for (int mf = 0; mf < 4; mf++) {
            int row0 = m0 + wm * 64 + mf * 16 + g;
            float v00 = fmaxf(acc[mf][nf][0] + bv0, 0.0f);
            float v01 = fmaxf(acc[mf][nf][1] + bv1, 0.0f);
            float v10 = fmaxf(acc[mf][nf][2] + bv0, 0.0f);
            float v11 = fmaxf(acc[mf][nf][3] + bv1, 0.0f);
            uint2 p0 = make_uint2(packsplit(v00), packsplit(v01));
            uint2 p1 = make_uint2(packsplit(v10), packsplit(v11));
            *(uint2*)&C[(size_t)row0 * HID + col]       = p0;
            *(uint2*)&C[(size_t)(row0 + 8) * HID + col] = p1;
        }
    }
}

// ---------------- final: 256->3 + weighted ensemble reduction ----------------
__global__ void k_final(const float* __restrict__ w4, const float* __restrict__ b4,
                        float* __restrict__ out) {
    __shared__ float w4s[HID * 3];
    __shared__ float b4s[3];
    for (int i = threadIdx.x; i < HID * 3; i += blockDim.x) w4s[i] = w4[i];
    if (threadIdx.x < 3) b4s[threadIdx.x] = b4[threadIdx.x];
    __syncthreads();
    int warp = threadIdx.x >> 5, lane = threadIdx.x & 31;
    int q = blockIdx.x * 8 + warp;
    float a0 = 0.f, a1 = 0.f, a2 = 0.f, scw = 0.f;
    for (int r = 0; r < 8; r++) {
        float cwv = g_cw[q * 8 + r];
        size_t hb = ((size_t)q * 8 + r) * HID;
        float s0 = 0.f, s1 = 0.f, s2 = 0.f;
        for (int c = lane; c < HID; c += 32) {
            uint32_t u = g_H2[hb + c];
            float hv = b2f((unsigned short)(u & 0xffff)) + b2f((unsigned short)(u >> 16));
            s0 += hv * w4s[c * 3 + 0];
            s1 += hv * w4s[c * 3 + 1];
            s2 += hv * w4s[c * 3 + 2];
        }
        a0 += cwv * s0; a1 += cwv * s1; a2 += cwv * s2;
        scw += cwv;
    }
#pragma unroll
    for (int o = 16; o > 0; o >>= 1) {
        a0 += __shfl_down_sync(0xffffffffu, a0, o);
        a1 += __shfl_down_sync(0xffffffffu, a1, o);
        a2 += __shfl_down_sync(0xffffffffu, a2, o);
    }
    if (lane == 0) {
        out[(size_t)q * 3 + 0] = a0 + scw * b4s[0];
        out[(size_t)q * 3 + 1] = a1 + scw * b4s[1];
        out[(size_t)q * 3 + 2] = a2 + scw * b4s[2];
    }
}

// ---------------- launch ----------------
extern "C" void kernel_launch(void* const* d_in, const int* in_sizes, int n_in,
                              void* d_out, int out_size) {
    const float* feat  = (const float*)d_in[0];
    const float* attn  = (const float*)d_in[1];
    const float* coord = (const float*)d_in[2];
    const float* cell  = (const float*)d_in[3];
    const float* w0 = (const float*)d_in[4];
    const float* b0 = (const float*)d_in[5];
    const float* w1 = (const float*)d_in[6];
    const float* b1 = (const float*)d_in[7];
    const float* w2 = (const float*)d_in[8];
    const float* b2 = (const float*)d_in[9];
    const float* w3 = (const float*)d_in[10];
    const float* b3 = (const float*)d_in[11];
    const float* w4 = (const float*)d_in[12];
    const float* b4 = (const float*)d_in[13];
    float* out = (float*)d_out;

    uint32_t *H1, *H2, *W0p, *Wp;
    cudaGetSymbolAddress((void**)&H1,  g_H1);
    cudaGetSymbolAddress((void**)&H2,  g_H2);
    cudaGetSymbolAddress((void**)&W0p, g_W0p32);
    cudaGetSymbolAddress((void**)&Wp,  g_Wp32);

    int prepn = KP0 * HID + 3 * HID * HID;
    k_prepw<<<(prepn + 255) / 256, 256>>>(w0, w1, w2, w3);
    k_unfold<<<(int)(((size_t)BQ * HWQ * D9 + 255) / 256), 256>>>(feat);
    k_argmax<<<(BQ * HWQ + 255) / 256, 256>>>(attn);
    k_top4a<<<BQ * NCHUNK, 256>>>(attn);
    k_top4b<<<1, 256>>>();
    k_build<<<(BQ * NQ + 255) / 256, 256>>>(coord, cell);

    k_gemm<0><<<NROW / 128, 256>>>(nullptr, W0p,              b0, H1);
    k_gemm<1><<<NROW / 128, 256>>>(H1, Wp,                    b1, H2);
    k_gemm<1><<<NROW / 128, 256>>>(H2, Wp + HID * HID,        b2, H1);
    k_gemm<1><<<NROW / 128, 256>>>(H1, Wp + 2 * HID * HID,    b3, H2);

    k_final<<<BQ * NQ / 8, 256>>>(w4, b4, out);
}

// round 4
// speedup vs baseline: 3.0139x; 1.5123x over previous
#include <cuda_runtime.h>
#include <cuda_bf16.h>
#include <cstdint>

// ---------------- problem constants ----------------
#define BQ   4
#define DQ   64
#define HQ   64
#define WQ   64
#define HWQ  4096
#define SQ   64
#define NQ   8192
#define KQ   4
#define D9   576
#define IN_DIM 580
#define HID  256
#define NROW 262144       // B*N*8 MLP rows
#define NPIX 16384        // B*HWQ distinct pixel rows
#define NCHUNK 64

// ---------------- device scratch ----------------
__device__ __align__(16) float    g_feat_rows[(size_t)BQ * HWQ * D9]; // 37.7MB
__device__ int      g_segm[BQ * HWQ];
__device__ float    g_partv[BQ * NCHUNK * SQ * KQ];
__device__ int      g_parti[BQ * NCHUNK * SQ * KQ];
__device__ float    g_top4v[BQ * SQ * KQ];
__device__ int      g_top4i[BQ * SQ * KQ];
__device__ uint32_t g_W0f32[D9 * HID];                  // packed (hi|lo<<16) bf16, w0 feat part
__device__ uint32_t g_Wp32[3 * HID * HID];              // w1..w3 packed
__device__ __align__(16) float    g_T[(size_t)NPIX * HID];   // T = feat_rows@w0f + b0 (16.8MB)
__device__ uint32_t g_H1[(size_t)NROW * HID];           // packed hidden activations
__device__ uint32_t g_H2[(size_t)NROW * HID];
__device__ int      g_rowsrc[NROW];                     // T-row index per MLP row
__device__ float    g_tail[(size_t)NROW * 4];
__device__ float    g_cw[NROW];

// ---------------- helpers ----------------
__device__ __forceinline__ unsigned short f2b(float x) {
    return __bfloat16_as_ushort(__float2bfloat16_rn(x));
}
__device__ __forceinline__ float b2f(unsigned short u) {
    return __bfloat162float(__ushort_as_bfloat16(u));
}
__device__ __forceinline__ uint32_t packsplit(float v) {
    unsigned short h = f2b(v);
    unsigned short l = f2b(v - b2f(h));
    return (uint32_t)h | ((uint32_t)l << 16);
}
__device__ __forceinline__ void mma_bf16(float* c, const unsigned* a,
                                         unsigned b0, unsigned b1) {
    asm volatile(
        "mma.sync.aligned.m16n8k16.row.col.f32.bf16.bf16.f32 "
        "{%0,%1,%2,%3},{%4,%5,%6,%7},{%8,%9},{%0,%1,%2,%3};\n"
        : "+f"(c[0]), "+f"(c[1]), "+f"(c[2]), "+f"(c[3])
        : "r"(a[0]), "r"(a[1]), "r"(a[2]), "r"(a[3]), "r"(b0), "r"(b1));
}
// top-4 insertion, lax.top_k tie semantics (value desc, index asc)
__device__ __forceinline__ void ins4(float v[4], int id[4], float val, int p) {
    if (!(val > v[3] || (val == v[3] && p < id[3]))) return;
    int pos = 3;
    while (pos > 0 && (val > v[pos - 1] || (val == v[pos - 1] && p < id[pos - 1]))) pos--;
    for (int q = 3; q > pos; q--) { v[q] = v[q - 1]; id[q] = id[q - 1]; }
    v[pos] = val; id[pos] = p;
}

// ---------------- prep: split weights into packed bf16 pairs ----------------
__global__ void k_prepw(const float* __restrict__ w0, const float* __restrict__ w1,
                        const float* __restrict__ w2, const float* __restrict__ w3) {
    int t = blockIdx.x * blockDim.x + threadIdx.x;
    const int n0 = D9 * HID;
    if (t < n0) {
        g_W0f32[t] = packsplit(w0[t]);   // rows 0..575 (feat part)
        return;
    }
    int t2 = t - n0;
    if (t2 >= 3 * HID * HID) return;
    int layer = t2 / (HID * HID);
    int i = t2 % (HID * HID);
    const float* w = (layer == 0) ? w1 : (layer == 1) ? w2 : w3;
    g_Wp32[t2] = packsplit(w[i]);
}

// ---------------- unfold ----------------
__global__ void k_unfold(const float* __restrict__ feat) {
    size_t tid = (size_t)blockIdx.x * blockDim.x + threadIdx.x;
    const size_t total = (size_t)BQ * HWQ * D9;
    if (tid >= total) return;
    int c9 = (int)(tid % D9);
    size_t r = tid / D9;
    int p = (int)(r % HWQ);
    int b = (int)(r / HWQ);
    int c = c9 / 9, kk = c9 % 9;
    int ki = kk / 3, kj = kk % 3;
    int i = p / WQ, j = p % WQ;
    int ii = i + ki - 1, jj = j + kj - 1;
    float v = 0.0f;
    if (ii >= 0 && ii < HQ && jj >= 0 && jj < WQ)
        v = feat[(((size_t)b * DQ + c) * HQ + ii) * WQ + jj];
    g_feat_rows[tid] = v;
}

// ---------------- argmax over S per (b,pixel) ----------------
__global__ void k_argmax(const float* __restrict__ attn) {
    int t = blockIdx.x * blockDim.x + threadIdx.x;
    if (t >= BQ * HWQ) return;
    const float* row = attn + (size_t)t * SQ;
    float best = row[0]; int bi = 0;
    for (int s = 1; s < SQ; s++) {
        float v = row[s];
        if (v > best) { best = v; bi = s; }
    }
    g_segm[t] = bi;
}

// ---------------- top4 stage A: partial top-4 per (b,chunk of 64 px,s) --------
__global__ void k_top4a(const float* __restrict__ attn) {
    __shared__ float tile[32][SQ + 1];
    __shared__ float sv[4][SQ][4];
    __shared__ int   si[4][SQ][4];
    int b = blockIdx.x >> 6;
    int chunk = blockIdx.x & 63;
    int tid = threadIdx.x;
    int s = tid & 63, sub = tid >> 6;
    float v[4]  = {-1e30f, -1e30f, -1e30f, -1e30f};
    int   id[4] = {0x7fffffff, 0x7fffffff, 0x7fffffff, 0x7fffffff};
    for (int t8 = 0; t8 < 2; t8++) {
        int p0 = chunk * 64 + t8 * 32;
        __syncthreads();
        for (int i = tid; i < 32 * SQ; i += 256) {
            int r = i >> 6, c = i & 63;
            tile[r][c] = attn[((size_t)(b * HWQ) + p0 + r) * SQ + c];
        }
        __syncthreads();
        for (int rr = 0; rr < 8; rr++) {
            int r = sub * 8 + rr;
            ins4(v, id, tile[r][s], p0 + r);
        }
    }
    for (int q = 0; q < 4; q++) { sv[sub][s][q] = v[q]; si[sub][s][q] = id[q]; }
    __syncthreads();
    if (sub == 0) {
        float fv[4]  = {-1e30f, -1e30f, -1e30f, -1e30f};
        int   fi[4]  = {0x7fffffff, 0x7fffffff, 0x7fffffff, 0x7fffffff};
        for (int ss = 0; ss < 4; ss++)
            for (int q = 0; q < 4; q++)
                ins4(fv, fi, sv[ss][s][q], si[ss][s][q]);
        int base = ((b * NCHUNK + chunk) * SQ + s) * 4;
        for (int q = 0; q < 4; q++) { g_partv[base + q] = fv[q]; g_parti[base + q] = fi[q]; }
    }
}

// ---------------- top4 stage B: merge chunks ----------------
__global__ void k_top4b() {
    int t = threadIdx.x;            // 256 threads: (b,s)
    int b = t >> 6, s = t & 63;
    float v[4]  = {-1e30f, -1e30f, -1e30f, -1e30f};
    int   id[4] = {0x7fffffff, 0x7fffffff, 0x7fffffff, 0x7fffffff};
    for (int ch = 0; ch < NCHUNK; ch++) {
        int base = ((b * NCHUNK + ch) * SQ + s) * 4;
        for (int q = 0; q < 4; q++) ins4(v, id, g_partv[base + q], g_parti[base + q]);
    }
    int o = (b * SQ + s) * 4;
    for (int q = 0; q < 4; q++) { g_top4v[o + q] = v[q]; g_top4i[o + q] = id[q]; }
}

// ---------------- build: per-row T-index + tails + weights ----------
__global__ void k_build(const float* __restrict__ coord,
                        const float* __restrict__ cell) {
    int q = blockIdx.x * blockDim.x + threadIdx.x;
    if (q >= BQ * NQ) return;
    int b = q >> 13;
    size_t cb = (size_t)q * 2;
    float c0 = coord[cb], c1 = coord[cb + 1];
    float rc0 = cell[cb] * (float)HQ, rc1 = cell[cb + 1] * (float)WQ;

    // ---- attention branch ----
    float pcf0 = (c0 + 1.0f) / 2.0f * (float)HQ;
    float pcf1 = (c1 + 1.0f) / 2.0f * (float)WQ;
    int pc0 = (int)pcf0; pc0 = max(0, min(HWQ - 1, pc0));
    int pc1 = (int)pcf1; pc1 = max(0, min(HWQ - 1, pc1));
    int pc1d = pc0 * HQ + pc1;
    pc1d = max(0, min(HWQ - 1, pc1d));
    int segm = g_segm[b * HWQ + pc1d];
    const float* tv = &g_top4v[(b * SQ + segm) * 4];
    const int*   ti = &g_top4i[(b * SQ + segm) * 4];
    float sum = tv[0] + tv[1] + tv[2] + tv[3];
    for (int k = 0; k < 4; k++) {
        int rc = ti[k];
        int rrc = rc - pc1d;
        float rel0 = (float)(rrc >> 6) * (1.0f / (float)HQ); // floor-div 64
        float rel1 = (float)(rrc & 63) * (1.0f / (float)WQ); // python mod 64
        int rowr = q * 8 + k;
        g_rowsrc[rowr] = rc;                                 // batch-0 row of T (faithful)
        g_tail[(size_t)rowr * 4 + 0] = rel0;
        g_tail[(size_t)rowr * 4 + 1] = rel1;
        g_tail[(size_t)rowr * 4 + 2] = rc0;
        g_tail[(size_t)rowr * 4 + 3] = rc1;
        g_cw[rowr] = 0.5f * (tv[k] / sum);
    }

    // ---- local ensemble ----
    const float offv[4][2] = {{-1.f, -1.f}, {-1.f, 1.f}, {1.f, -1.f}, {1.f, 1.f}};
    float area[4];
    for (int j = 0; j < 4; j++) {
        float rx = 1.0f / (float)HQ, ry = 1.0f / (float)WQ;
        float cc0 = c0 + offv[j][0] * rx + 1e-6f;
        float cc1 = c1 + offv[j][1] * ry + 1e-6f;
        cc0 = fminf(fmaxf(cc0, -1.0f + 1e-6f), 1.0f - 1e-6f);
        cc1 = fminf(fmaxf(cc1, -1.0f + 1e-6f), 1.0f - 1e-6f);
        float fy = ((cc0 + 1.0f) * (float)HQ - 1.0f) / 2.0f;
        float fx = ((cc1 + 1.0f) * (float)WQ - 1.0f) / 2.0f;
        int iy = (int)rintf(fy); iy = max(0, min(HQ - 1, iy));
        int ix = (int)rintf(fx); ix = max(0, min(WQ - 1, ix));
        int flat = iy * WQ + ix;
        float qc0 = -1.0f + (2.0f * (float)iy + 1.0f) / (float)HQ;
        float qc1 = -1.0f + (2.0f * (float)ix + 1.0f) / (float)WQ;
        float r0 = (c0 - qc0) * (float)HQ;
        float r1 = (c1 - qc1) * (float)WQ;
        int rowr = q * 8 + 4 + j;
        g_rowsrc[rowr] = b * HWQ + flat;
        g_tail[(size_t)rowr * 4 + 0] = r0;
        g_tail[(size_t)rowr * 4 + 1] = r1;
        g_tail[(size_t)rowr * 4 + 2] = rc0;
        g_tail[(size_t)rowr * 4 + 3] = rc1;
        area[j] = fabsf(r0 * r1) + 1e-9f;
    }
    float tot = area[0] + area[1] + area[2] + area[3];
    for (int j = 0; j < 4; j++) g_cw[q * 8 + 4 + j] = 0.5f * (area[3 - j] / tot);
}

// ---------------- GEMM, bf16x3 mma. BM=128 BN=256 BK=16, 256 thr ----------------
// MODE 0: T-producer. A = g_feat_rows rows (f32, lda=576, contiguous), K=576,
//         C = g_T f32, +bias, NO relu.
// MODE 1: layer1. A row r: relu(T[rowsrc[r]] + tail(r)·w0tail), K=256, C packed.
// MODE 2: hidden. A packed u32, K=256, C packed.
template<int MODE>
__global__ void __launch_bounds__(256)
k_gemm(const float* __restrict__ Af, const uint32_t* __restrict__ Au,
       const uint32_t* __restrict__ W, const float* __restrict__ bias,
       const float* __restrict__ w0tail,
       float* __restrict__ Cf, uint32_t* __restrict__ Cu) {
    constexpr int T = (MODE == 0) ? (D9 / 16) : (HID / 16);
    constexpr int LDA = (MODE == 0) ? D9 : HID;
    __shared__ __align__(16) unsigned short AsH[128][24];
    __shared__ __align__(16) unsigned short AsL[128][24];
    __shared__ __align__(16) unsigned short BsH[256][24];
    __shared__ __align__(16) unsigned short BsL[256][24];
    __shared__ float sw0t[4 * HID];

    int tid = threadIdx.x;
    int m0 = blockIdx.x * 128;
    int arow = tid >> 1, ahalf = tid & 1;

    if (MODE == 1) {
        for (int i = tid; i < 4 * HID; i += 256) sw0t[i] = w0tail[i];
    }
    __syncthreads();

    int src = 0;
    float t0 = 0.f, t1 = 0.f, t2 = 0.f, t3 = 0.f;
    if (MODE == 1) {
        src = g_rowsrc[m0 + arow];
        const float* tp = &g_tail[(size_t)(m0 + arow) * 4];
        t0 = tp[0]; t1 = tp[1]; t2 = tp[2]; t3 = tp[3];
    }

    float    af[8];
    uint32_t au[8];
    uint32_t bw[16];

    auto loadT = [&](int t) {
        int kk = t * 16;
        if (MODE == 0) {
            const float* ap = Af + (size_t)(m0 + arow) * LDA + kk + ahalf * 8;
            float4 f0 = *(const float4*)ap;
            float4 f1 = *(const float4*)(ap + 4);
            af[0] = f0.x; af[1] = f0.y; af[2] = f0.z; af[3] = f0.w;
            af[4] = f1.x; af[5] = f1.y; af[6] = f1.z; af[7] = f1.w;
        } else if (MODE == 1) {
            const float* ap = Af + (size_t)src * HID + kk + ahalf * 8;
            float4 f0 = *(const float4*)ap;
            float4 f1 = *(const float4*)(ap + 4);
            af[0] = f0.x; af[1] = f0.y; af[2] = f0.z; af[3] = f0.w;
            af[4] = f1.x; af[5] = f1.y; af[6] = f1.z; af[7] = f1.w;
#pragma unroll
            for (int j = 0; j < 8; j++) {
                int c = kk + ahalf * 8 + j;
                float v = af[j] + t0 * sw0t[c] + t1 * sw0t[HID + c]
                                + t2 * sw0t[2 * HID + c] + t3 * sw0t[3 * HID + c];
                af[j] = fmaxf(v, 0.0f);
            }
        } else {
            const uint32_t* ap = Au + (size_t)(m0 + arow) * HID + kk + ahalf * 8;
            uint4 u0 = *(const uint4*)ap;
            uint4 u1 = *(const uint4*)(ap + 4);
            au[0] = u0.x; au[1] = u0.y; au[2] = u0.z; au[3] = u0.w;
            au[4] = u1.x; au[5] = u1.y; au[6] = u1.z; au[7] = u1.w;
        }
#pragma unroll
        for (int r = 0; r < 16; r++) bw[r] = W[(size_t)(kk + r) * HID + tid];
    };
    auto storeT = [&]() {
#pragma unroll
        for (int j = 0; j < 8; j++) {
            unsigned short h, l;
            if (MODE != 2) {
                float v = af[j];
                h = f2b(v);
                l = f2b(v - b2f(h));
            } else {
                h = (unsigned short)(au[j] & 0xffff);
                l = (unsigned short)(au[j] >> 16);
            }
            AsH[arow][ahalf * 8 + j] = h;
            AsL[arow][ahalf * 8 + j] = l;
        }
#pragma unroll
        for (int r = 0; r < 16; r++) {
            BsH[tid][r] = (unsigned short)(bw[r] & 0xffff);
            BsL[tid][r] = (unsigned short)(bw[r] >> 16);
        }
    };

    int warp = tid >> 5, lane = tid & 31;
    int wm = warp & 1, wn = warp >> 1;
    int g = lane >> 2, tg = lane & 3;

    float acc[4][8][4];
#pragma unroll
    for (int mf = 0; mf < 4; mf++)
#pragma unroll
        for (int nf = 0; nf < 8; nf++)
#pragma unroll
            for (int ci = 0; ci < 4; ci++) acc[mf][nf][ci] = 0.0f;

    loadT(0);
    for (int t = 0; t < T; t++) {
        __syncthreads();
        storeT();
        __syncthreads();
        if (t + 1 < T) loadT(t + 1);

        unsigned aH[4][4], aL[4][4];
#pragma unroll
        for (int mf = 0; mf < 4; mf++) {
            int r0 = wm * 64 + mf * 16 + g;
            aH[mf][0] = *(const uint32_t*)&AsH[r0    ][2 * tg];
            aH[mf][1] = *(const uint32_t*)&AsH[r0 + 8][2 * tg];
            aH[mf][2] = *(const uint32_t*)&AsH[r0    ][2 * tg + 8];
            aH[mf][3] = *(const uint32_t*)&AsH[r0 + 8][2 * tg + 8];
            aL[mf][0] = *(const uint32_t*)&AsL[r0    ][2 * tg];
            aL[mf][1] = *(const uint32_t*)&AsL[r0 + 8][2 * tg];
            aL[mf][2] = *(const uint32_t*)&AsL[r0    ][2 * tg + 8];
            aL[mf][3] = *(const uint32_t*)&AsL[r0 + 8][2 * tg + 8];
        }
#pragma unroll
        for (int nf = 0; nf < 8; nf++) {
            int c0 = wn * 64 + nf * 8 + g;
            unsigned bH0 = *(const uint32_t*)&BsH[c0][2 * tg];
            unsigned bH1 = *(const uint32_t*)&BsH[c0][2 * tg + 8];
            unsigned bL0 = *(const uint32_t*)&BsL[c0][2 * tg];
            unsigned bL1 = *(const uint32_t*)&BsL[c0][2 * tg + 8];
#pragma unroll
            for (int mf = 0; mf < 4; mf++) {
                mma_bf16(acc[mf][nf], aH[mf], bH0, bH1);   // hi*hi
                mma_bf16(acc[mf][nf], aH[mf], bL0, bL1);   // hi*lo
                mma_bf16(acc[mf][nf], aL[mf], bH0, bH1);   // lo*hi
            }
        }
    }

    // ---- epilogue ----
#pragma unroll
    for (int nf = 0; nf < 8; nf++) {
        int col = wn * 64 + nf * 8 + tg * 2;
        float bv0 = bias[col], bv1 = bias[col + 1];
#pragma unroll
        for (int mf = 0; mf < 4; mf++) {
            int row0 = m0 + wm * 64 + mf * 16 + g;
            if (MODE == 0) {
                float2 p0 = make_float2(acc[mf][nf][0] + bv0, acc[mf][nf][1] + bv1);
                float2 p1 = make_float2(acc[mf][nf][2] + bv0, acc[mf][nf][3] + bv1);
                *(float2*)&Cf[(size_t)row0 * HID + col]       = p0;
                *(float2*)&Cf[(size_t)(row0 + 8) * HID + col] = p1;
            } else {
                float v00 = fmaxf(acc[mf][nf][0] + bv0, 0.0f);
                float v01 = fmaxf(acc[mf][nf][1] + bv1, 0.0f);
                float v10 = fmaxf(acc[mf][nf][2] + bv0, 0.0f);
                float v11 = fmaxf(acc[mf][nf][3] + bv1, 0.0f);
                uint2 p0 = make_uint2(packsplit(v00), packsplit(v01));
                uint2 p1 = make_uint2(packsplit(v10), packsplit(v11));
                *(uint2*)&Cu[(size_t)row0 * HID + col]       = p0;
                *(uint2*)&Cu[(size_t)(row0 + 8) * HID + col] = p1;
            }
        }
    }
}

// ---------------- final: 256->3 + weighted ensemble reduction ----------------
__global__ void k_final(const uint32_t* __restrict__ H,
                        const float* __restrict__ w4, const float* __restrict__ b4,
                        float* __restrict__ out) {
    __shared__ float w4s[HID * 3];
    __shared__ float b4s[3];
    for (int i = threadIdx.x; i < HID * 3; i += blockDim.x) w4s[i] = w4[i];
    if (threadIdx.x < 3) b4s[threadIdx.x] = b4[threadIdx.x];
    __syncthreads();
    int warp = threadIdx.x >> 5, lane = threadIdx.x & 31;
    int q = blockIdx.x * 8 + warp;
    float a0 = 0.f, a1 = 0.f, a2 = 0.f, scw = 0.f;
    for (int r = 0; r < 8; r++) {
        float cwv = g_cw[q * 8 + r];
        size_t hb = ((size_t)q * 8 + r) * HID;
        float s0 = 0.f, s1 = 0.f, s2 = 0.f;
        for (int c = lane; c < HID; c += 32) {
            uint32_t u = H[hb + c];
            float hv = b2f((unsigned short)(u & 0xffff)) + b2f((unsigned short)(u >> 16));
            s0 += hv * w4s[c * 3 + 0];
            s1 += hv * w4s[c * 3 + 1];
            s2 += hv * w4s[c * 3 + 2];
        }
        a0 += cwv * s0; a1 += cwv * s1; a2 += cwv * s2;
        scw += cwv;
    }
#pragma unroll
    for (int o = 16; o > 0; o >>= 1) {
        a0 += __shfl_down_sync(0xffffffffu, a0, o);
        a1 += __shfl_down_sync(0xffffffffu, a1, o);
        a2 += __shfl_down_sync(0xffffffffu, a2, o);
    }
    if (lane == 0) {
        out[(size_t)q * 3 + 0] = a0 + scw * b4s[0];
        out[(size_t)q * 3 + 1] = a1 + scw * b4s[1];
        out[(size_t)q * 3 + 2] = a2 + scw * b4s[2];
    }
}

// ---------------- launch ----------------
extern "C" void kernel_launch(void* const* d_in, const int* in_sizes, int n_in,
                              void* d_out, int out_size) {
    const float* feat  = (const float*)d_in[0];
    const float* attn  = (const float*)d_in[1];
    const float* coord = (const float*)d_in[2];
    const float* cell  = (const float*)d_in[3];
    const float* w0 = (const float*)d_in[4];
    const float* b0 = (const float*)d_in[5];
    const float* w1 = (const float*)d_in[6];
    const float* b1 = (const float*)d_in[7];
    const float* w2 = (const float*)d_in[8];
    const float* b2 = (const float*)d_in[9];
    const float* w3 = (const float*)d_in[10];
    const float* b3 = (const float*)d_in[11];
    const float* w4 = (const float*)d_in[12];
    const float* b4 = (const float*)d_in[13];
    float* out = (float*)d_out;

    float *Tt, *FR;
    uint32_t *H1, *H2, *W0f, *Wp;
    cudaGetSymbolAddress((void**)&Tt,  g_T);
    cudaGetSymbolAddress((void**)&FR,  g_feat_rows);
    cudaGetSymbolAddress((void**)&H1,  g_H1);
    cudaGetSymbolAddress((void**)&H2,  g_H2);
    cudaGetSymbolAddress((void**)&W0f, g_W0f32);
    cudaGetSymbolAddress((void**)&Wp,  g_Wp32);
    const float* w0tail = w0 + (size_t)D9 * HID;   // rows 576..579

    int prepn = D9 * HID + 3 * HID * HID;
    k_prepw<<<(prepn + 255) / 256, 256>>>(w0, w1, w2, w3);
    k_unfold<<<(int)(((size_t)BQ * HWQ * D9 + 255) / 256), 256>>>(feat);
    k_argmax<<<(BQ * HWQ + 255) / 256, 256>>>(attn);
    k_top4a<<<BQ * NCHUNK, 256>>>(attn);
    k_top4b<<<1, 256>>>();
    k_build<<<(BQ * NQ + 255) / 256, 256>>>(coord, cell);

    // T = feat_rows @ w0_feat + b0  (16384 x 256)
    k_gemm<0><<<NPIX / 128, 256>>>(FR, nullptr, W0f, b0, nullptr, Tt, nullptr);
    // layer1: h1 = relu(relu(T[src]+tail·w0t) @ w1 + b1)
    k_gemm<1><<<NROW / 128, 256>>>(Tt, nullptr, Wp,               b1, w0tail, nullptr, H1);
    // layers 2,3
    k_gemm<2><<<NROW / 128, 256>>>(nullptr, H1, Wp + HID * HID,   b2, nullptr, nullptr, H2);
    k_gemm<2><<<NROW / 128, 256>>>(nullptr, H2, Wp + 2 * HID * HID, b3, nullptr, nullptr, H1);

    k_final<<<BQ * NQ / 8, 256>>>(H1, w4, b4, out);
}